// round 15
// baseline (speedup 1.0000x reference)
#include <cuda_runtime.h>
#include <cstdint>
#include <cstddef>

// Problem constants
#define B_    256
#define S_    512
#define EMB_  256
#define KER_  5
#define NF_   256
#define HID_  128
#define T_    508            // S - KER + 1
#define M_    (T_ * B_)      // 130048 rows (r = t*B + b)
#define KCONV (KER_ * EMB_)  // 1280
#define GATES 512            // 4*HID

typedef unsigned long long u64;

// ---------------- f32x2 packed-FMA helpers (proven clean) ------------------
__device__ __forceinline__ void fma2(u64& d, u64 a, u64 b) {
  asm("fma.rn.f32x2 %0, %1, %2, %0;" : "+l"(d) : "l"(a), "l"(b));
}
__device__ __forceinline__ u64 pack2(float x, float y) {
  u64 r; asm("mov.b64 %0, {%1, %2};" : "=l"(r) : "f"(x), "f"(y)); return r;
}
__device__ __forceinline__ float2 unpack2(u64 p) {
  float2 f; asm("mov.b64 {%0, %1}, %2;" : "=f"(f.x), "=f"(f.y) : "l"(p));
  return f;
}
__device__ __forceinline__ uint32_t smem_addr_u32(const void* p) {
  uint32_t a;
  asm("{ .reg .u64 t; cvta.to.shared.u64 t, %1; cvt.u32.u64 %0, t; }"
      : "=r"(a) : "l"(p));
  return a;
}
__device__ __forceinline__ uint32_t cluster_rank() {
  uint32_t r; asm("mov.u32 %0, %%cluster_ctarank;" : "=r"(r)); return r;
}
__device__ __forceinline__ uint32_t mapa_u32(uint32_t la, uint32_t rank) {
  uint32_t r;
  asm("mapa.shared::cluster.u32 %0, %1, %2;" : "=r"(r) : "r"(la), "r"(rank));
  return r;
}
__device__ __forceinline__ void st_cluster_u64(uint32_t addr, u64 v) {
  asm volatile("st.shared::cluster.u64 [%0], %1;" :: "r"(addr), "l"(v)
               : "memory");
}

// Scratch (fp32 only)
__device__ float g_F [(size_t)M_ * NF_];         // conv+relu    [r][nf]
__device__ float g_Xg[(size_t)M_ * GATES];       // x-gates+bias [r][4H]

// ---------------------------------------------------------------------------
// K1: conv GEMM with FUSED embedding gather. BM=BN=128, BK=16, 128 thr,
// 16x8/thread FFMA2, double-buffered smem, 2 CTAs/SM (R14-proven core).
// A row r=(t,b): per-CTA t is CONSTANT (128-row block = half batch of one t).
// A staging reads emb[text[b*512+s]] directly (s = t + c/256, col = c%256).
// ---------------------------------------------------------------------------
__global__ void __launch_bounds__(128, 2)
sgemm_conv_kernel(const int* __restrict__ text,
                  const float* __restrict__ emb,
                  const float* __restrict__ W,
                  const float* __restrict__ bias0) {
  __shared__ float As[2][16][128];
  __shared__ float Bs[2][16][128];

  const int tid  = threadIdx.x;
  const int row0 = blockIdx.y * 128;
  const int col0 = blockIdx.x * 128;
  const int tr   = (tid >> 4) << 4;
  const int tc   = (tid & 15) << 3;
  const int ms   = tid >> 2;
  const int kq   = (tid & 3) * 4;

  u64 acc2[8][8];
#pragma unroll
  for (int i = 0; i < 8; i++)
#pragma unroll
    for (int j = 0; j < 8; j++) acc2[i][j] = 0ull;

  // per-CTA constant t; per-thread batch indices for the 4 staged rows
  const int tt = row0 >> 8;
  int bI[4];
#pragma unroll
  for (int i = 0; i < 4; i++) bI[i] = (row0 + ms + i * 32) & 255;

  size_t boff[4];
#pragma unroll
  for (int i = 0; i < 4; i++)
    boff[i] = (size_t)(col0 + ms + i * 32) * KCONV;

  const int KT = KCONV >> 4;   // 80

  // prologue: tile 0
  {
    int c = kq;                     // < 256 -> s = tt, col = c
    int s = tt, col = c;
#pragma unroll
    for (int i = 0; i < 4; i++) {
      int m = ms + i * 32;
      int tok = text[bI[i] * S_ + s];
      float4 va = *(const float4*)(emb + (size_t)tok * EMB_ + col);
      float4 vb = *(const float4*)(W + boff[i] + c);
      As[0][kq + 0][m] = va.x; As[0][kq + 1][m] = va.y;
      As[0][kq + 2][m] = va.z; As[0][kq + 3][m] = va.w;
      Bs[0][kq + 0][m] = vb.x; Bs[0][kq + 1][m] = vb.y;
      Bs[0][kq + 2][m] = vb.z; Bs[0][kq + 3][m] = vb.w;
    }
  }
  __syncthreads();

  for (int kt = 0; kt < KT; kt++) {
    const int cur = kt & 1;
    float4 pa[4], pb[4];
    const bool pf = (kt + 1 < KT);
    if (pf) {
      int c = ((kt + 1) << 4) + kq;
      int s = tt + (c >> 8), col = c & 255;
#pragma unroll
      for (int i = 0; i < 4; i++) {
        int tok = text[bI[i] * S_ + s];
        pa[i] = *(const float4*)(emb + (size_t)tok * EMB_ + col);
        pb[i] = *(const float4*)(W + boff[i] + c);
      }
    }
#pragma unroll
    for (int kk = 0; kk < 16; kk++) {
      ulonglong2 a01 = *(const ulonglong2*)&As[cur][kk][tr];
      ulonglong2 a23 = *(const ulonglong2*)&As[cur][kk][tr +  4];
      ulonglong2 a45 = *(const ulonglong2*)&As[cur][kk][tr +  8];
      ulonglong2 a67 = *(const ulonglong2*)&As[cur][kk][tr + 12];
      u64 av[8] = {a01.x, a01.y, a23.x, a23.y, a45.x, a45.y, a67.x, a67.y};
      float4 b03 = *(const float4*)&Bs[cur][kk][tc];
      float4 b47 = *(const float4*)&Bs[cur][kk][tc + 4];
      u64 bd[8];
      bd[0] = pack2(b03.x, b03.x); bd[1] = pack2(b03.y, b03.y);
      bd[2] = pack2(b03.z, b03.z); bd[3] = pack2(b03.w, b03.w);
      bd[4] = pack2(b47.x, b47.x); bd[5] = pack2(b47.y, b47.y);
      bd[6] = pack2(b47.z, b47.z); bd[7] = pack2(b47.w, b47.w);
#pragma unroll
      for (int i = 0; i < 8; i++)
#pragma unroll
        for (int j = 0; j < 8; j++) fma2(acc2[i][j], av[i], bd[j]);
    }
    if (pf) {
      const int nxt = cur ^ 1;
#pragma unroll
      for (int i = 0; i < 4; i++) {
        int m = ms + i * 32;
        As[nxt][kq + 0][m] = pa[i].x; As[nxt][kq + 1][m] = pa[i].y;
        As[nxt][kq + 2][m] = pa[i].z; As[nxt][kq + 3][m] = pa[i].w;
        Bs[nxt][kq + 0][m] = pb[i].x; Bs[nxt][kq + 1][m] = pb[i].y;
        Bs[nxt][kq + 2][m] = pb[i].z; Bs[nxt][kq + 3][m] = pb[i].w;
      }
    }
    __syncthreads();
  }

#pragma unroll
  for (int i = 0; i < 8; i++) {
    float vlo[8], vhi[8];
#pragma unroll
    for (int j = 0; j < 8; j++) {
      int n = col0 + tc + j;
      float2 p = unpack2(acc2[i][j]);
      vlo[j] = fmaxf(p.x + bias0[n], 0.f);
      vhi[j] = fmaxf(p.y + bias0[n], 0.f);
    }
    float* c0 = &g_F[(size_t)(row0 + tr + 2 * i)     * NF_ + col0 + tc];
    float* c1 = &g_F[(size_t)(row0 + tr + 2 * i + 1) * NF_ + col0 + tc];
    *(float4*)(c0)     = *(float4*)&vlo[0];
    *(float4*)(c0 + 4) = *(float4*)&vlo[4];
    *(float4*)(c1)     = *(float4*)&vhi[0];
    *(float4*)(c1 + 4) = *(float4*)&vhi[4];
  }
}

// ---------------------------------------------------------------------------
// K2: x-gates GEMM, BM=128 BN=256 BK=16, 256 thr (16x8/thread), 1 CTA/SM.
// Halves A traffic vs grid.x=4 (each A row-block now read 2x, not 4x).
// ---------------------------------------------------------------------------
__global__ void __launch_bounds__(256, 1)
sgemm_x_kernel(const float* __restrict__ W,
               const float* __restrict__ b_ih,
               const float* __restrict__ b_hh) {
  __shared__ float As[2][16][128];
  __shared__ float Bs[2][16][256];

  const int tid  = threadIdx.x;
  const int row0 = blockIdx.y * 128;
  const int col0 = blockIdx.x * 256;
  const int tr   = (tid >> 5) << 4;   // 8 row groups x 16
  const int tc   = (tid & 31) << 3;   // 32 col groups x 8
  const int ms   = tid >> 2;          // 0..63
  const int kq   = (tid & 3) * 4;

  u64 acc2[8][8];
#pragma unroll
  for (int i = 0; i < 8; i++)
#pragma unroll
    for (int j = 0; j < 8; j++) acc2[i][j] = 0ull;

  size_t aoff[2], boff[4];
#pragma unroll
  for (int i = 0; i < 2; i++)
    aoff[i] = (size_t)(row0 + ms + i * 64) * NF_;
#pragma unroll
  for (int i = 0; i < 4; i++)
    boff[i] = (size_t)(col0 + ms + i * 64) * NF_;

  const int KT = NF_ >> 4;   // 16

  // prologue
#pragma unroll
  for (int i = 0; i < 2; i++) {
    int m = ms + i * 64;
    float4 va = *(const float4*)(g_F + aoff[i] + kq);
    As[0][kq + 0][m] = va.x; As[0][kq + 1][m] = va.y;
    As[0][kq + 2][m] = va.z; As[0][kq + 3][m] = va.w;
  }
#pragma unroll
  for (int i = 0; i < 4; i++) {
    int m = ms + i * 64;
    float4 vb = *(const float4*)(W + boff[i] + kq);
    Bs[0][kq + 0][m] = vb.x; Bs[0][kq + 1][m] = vb.y;
    Bs[0][kq + 2][m] = vb.z; Bs[0][kq + 3][m] = vb.w;
  }
  __syncthreads();

  for (int kt = 0; kt < KT; kt++) {
    const int cur = kt & 1;
    float4 pa[2], pb[4];
    const bool pf = (kt + 1 < KT);
    if (pf) {
      int k0 = (kt + 1) << 4;
#pragma unroll
      for (int i = 0; i < 2; i++)
        pa[i] = *(const float4*)(g_F + aoff[i] + k0 + kq);
#pragma unroll
      for (int i = 0; i < 4; i++)
        pb[i] = *(const float4*)(W + boff[i] + k0 + kq);
    }
#pragma unroll
    for (int kk = 0; kk < 16; kk++) {
      ulonglong2 a01 = *(const ulonglong2*)&As[cur][kk][tr];
      ulonglong2 a23 = *(const ulonglong2*)&As[cur][kk][tr +  4];
      ulonglong2 a45 = *(const ulonglong2*)&As[cur][kk][tr +  8];
      ulonglong2 a67 = *(const ulonglong2*)&As[cur][kk][tr + 12];
      u64 av[8] = {a01.x, a01.y, a23.x, a23.y, a45.x, a45.y, a67.x, a67.y};
      float4 b03 = *(const float4*)&Bs[cur][kk][tc];
      float4 b47 = *(const float4*)&Bs[cur][kk][tc + 4];
      u64 bd[8];
      bd[0] = pack2(b03.x, b03.x); bd[1] = pack2(b03.y, b03.y);
      bd[2] = pack2(b03.z, b03.z); bd[3] = pack2(b03.w, b03.w);
      bd[4] = pack2(b47.x, b47.x); bd[5] = pack2(b47.y, b47.y);
      bd[6] = pack2(b47.z, b47.z); bd[7] = pack2(b47.w, b47.w);
#pragma unroll
      for (int i = 0; i < 8; i++)
#pragma unroll
        for (int j = 0; j < 8; j++) fma2(acc2[i][j], av[i], bd[j]);
    }
    if (pf) {
      const int nxt = cur ^ 1;
#pragma unroll
      for (int i = 0; i < 2; i++) {
        int m = ms + i * 64;
        As[nxt][kq + 0][m] = pa[i].x; As[nxt][kq + 1][m] = pa[i].y;
        As[nxt][kq + 2][m] = pa[i].z; As[nxt][kq + 3][m] = pa[i].w;
      }
#pragma unroll
      for (int i = 0; i < 4; i++) {
        int m = ms + i * 64;
        Bs[nxt][kq + 0][m] = pb[i].x; Bs[nxt][kq + 1][m] = pb[i].y;
        Bs[nxt][kq + 2][m] = pb[i].z; Bs[nxt][kq + 3][m] = pb[i].w;
      }
    }
    __syncthreads();
  }

#pragma unroll
  for (int i = 0; i < 8; i++) {
    float vlo[8], vhi[8];
#pragma unroll
    for (int j = 0; j < 8; j++) {
      int n = col0 + tc + j;
      float2 p = unpack2(acc2[i][j]);
      float bb = b_ih[n] + b_hh[n];
      vlo[j] = p.x + bb;
      vhi[j] = p.y + bb;
    }
    float* c0 = &g_Xg[(size_t)(row0 + tr + 2 * i)     * GATES + col0 + tc];
    float* c1 = &g_Xg[(size_t)(row0 + tr + 2 * i + 1) * GATES + col0 + tc];
    *(float4*)(c0)     = *(float4*)&vlo[0];
    *(float4*)(c0 + 4) = *(float4*)&vlo[4];
    *(float4*)(c1)     = *(float4*)&vhi[0];
    *(float4*)(c1 + 4) = *(float4*)&vhi[4];
  }
}

// ---------------------------------------------------------------------------
// K3: persistent LSTM recurrence, cluster-of-2 DSMEM (R14 core) with:
//  - no redundant __syncthreads (barrier.cluster syncs own CTA too)
//  - x-gates(t+1) prefetched BEFORE the cluster barrier (latency hidden)
// ---------------------------------------------------------------------------
#define WP_FLOATS (128 * 64 * 4)             // 32768 floats = 128KB
#define HS_FLOATS (2 * 4 * 256)              // 2048 floats = 8KB
#define RSMEM     ((WP_FLOATS + HS_FLOATS) * 4)

__global__ void __launch_bounds__(128, 1) __cluster_dims__(2, 1, 1)
lstm2_kernel(const float* __restrict__ w_hh,
             const float* __restrict__ h0,
             float* __restrict__ out) {
  extern __shared__ float sm[];
  float* Wp = sm;                 // [k][jl][g], 64 jl of this half
  float* hs = sm + WP_FLOATS;     // [buf][b][2k..2k+1]

  const int tid = threadIdx.x;
  const int bid = blockIdx.x;
  const int jh  = bid & 1;        // hidden half (0..1)
  const int bt  = bid >> 1;       // batch tile (4 rows), 64 tiles
  const uint32_t peer = cluster_rank() ^ 1u;

  for (int i = tid; i < WP_FLOATS; i += 128) {
    int k = i >> 8, rem = i & 255, jl = rem >> 2, g = rem & 3;
    Wp[i] = w_hh[(size_t)(g * 128 + jh * 64 + jl) * 128 + k];
  }
  {
    float4 v = ((const float4*)(h0 + bt * 4 * HID_))[tid];
    int b = tid >> 5, k4 = tid & 31;
    float* d = &hs[b * 256 + k4 * 8];
    *(float4*)(d)     = make_float4(v.x, v.x, v.y, v.y);
    *(float4*)(d + 4) = make_float4(v.z, v.z, v.w, v.w);
  }
  __syncthreads();

  const int jl = tid & 63;
  const int bp = tid >> 6;
  const int jg = jh * 64 + jl;
  const int b0 = bt * 4 + 2 * bp;
  const uint32_t hs_u32 = smem_addr_u32(hs);

  float c0 = 0.f, c1 = 0.f;

  // prefetch x-gates for t = 0
  float x0[4], x1[4];
  {
    const float* xg = g_Xg + (size_t)b0 * GATES;
#pragma unroll
    for (int g = 0; g < 4; g++) {
      x0[g] = xg[g * HID_ + jg];
      x1[g] = xg[GATES + g * HID_ + jg];
    }
  }

  for (int t = 0; t < T_; t++) {
    u64 aA0 = 0ull, aB0 = 0ull, aA1 = 0ull, aB1 = 0ull;
    const float* h0r = &hs[(t & 1) * 1024 + (2 * bp)     * 256];
    const float* h1r = &hs[(t & 1) * 1024 + (2 * bp + 1) * 256];
#pragma unroll 8
    for (int k = 0; k < HID_; k += 4) {
      ulonglong2 pa  = *(const ulonglong2*)(h0r + 2 * k);
      ulonglong2 pa2 = *(const ulonglong2*)(h0r + 2 * k + 4);
      ulonglong2 pb  = *(const ulonglong2*)(h1r + 2 * k);
      ulonglong2 pb2 = *(const ulonglong2*)(h1r + 2 * k + 4);
      u64 hd0[4] = {pa.x, pa.y, pa2.x, pa2.y};
      u64 hd1[4] = {pb.x, pb.y, pb2.x, pb2.y};
#pragma unroll
      for (int kk = 0; kk < 4; kk++) {
        ulonglong2 wv = *(const ulonglong2*)&Wp[((k + kk) * 64 + jl) * 4];
        fma2(aA0, hd0[kk], wv.x); fma2(aB0, hd0[kk], wv.y);
        fma2(aA1, hd1[kk], wv.x); fma2(aB1, hd1[kk], wv.y);
      }
    }

    float2 pA0 = unpack2(aA0), pB0 = unpack2(aB0);
    float2 pA1 = unpack2(aA1), pB1 = unpack2(aB1);

    float i0 = 1.f / (1.f + __expf(-(pA0.x + x0[0])));
    float f0 = 1.f / (1.f + __expf(-(pA0.y + x0[1])));
    float g0 = tanhf(pB0.x + x0[2]);
    float o0 = 1.f / (1.f + __expf(-(pB0.y + x0[3])));
    c0 = f0 * c0 + i0 * g0;
    float h0v = o0 * tanhf(c0);

    float i1 = 1.f / (1.f + __expf(-(pA1.x + x1[0])));
    float f1 = 1.f / (1.f + __expf(-(pA1.y + x1[1])));
    float g1 = tanhf(pB1.x + x1[2]);
    float o1 = 1.f / (1.f + __expf(-(pB1.y + x1[3])));
    c1 = f1 * c1 + i1 * g1;
    float h1v = o1 * tanhf(c1);

    if (t == T_ - 1) {
      out[b0 * HID_ + jg]        = h0v;
      out[(b0 + 1) * HID_ + jg]  = h1v;
    } else {
      // h(t+1) duplicated into BOTH CTAs' buffer (t+1)&1
      const int fo0 = ((t + 1) & 1) * 1024 + (2 * bp) * 256 + 2 * jg;
      const int fo1 = fo0 + 256;
      u64 p0 = pack2(h0v, h0v);
      u64 p1 = pack2(h1v, h1v);
      *(u64*)&hs[fo0] = p0;
      *(u64*)&hs[fo1] = p1;
      st_cluster_u64(mapa_u32(hs_u32 + fo0 * 4, peer), p0);
      st_cluster_u64(mapa_u32(hs_u32 + fo1 * 4, peer), p1);

      // prefetch x-gates(t+1) BEFORE the barrier (latency overlaps wait)
      const float* xg = g_Xg + ((size_t)(t + 1) * B_ + b0) * GATES;
#pragma unroll
      for (int g = 0; g < 4; g++) {
        x0[g] = xg[g * HID_ + jg];
        x1[g] = xg[GATES + g * HID_ + jg];
      }

      // arrive = release (covers smem + DSMEM stores) and syncs own CTA too
      asm volatile("barrier.cluster.arrive.aligned;" ::: "memory");
      asm volatile("barrier.cluster.wait.aligned;"   ::: "memory");
    }
  }
}

// ---------------------------------------------------------------------------
extern "C" void kernel_launch(void* const* d_in, const int* in_sizes, int n_in,
                              void* d_out, int out_size) {
  const int*   text   = (const int*)  d_in[0];
  const float* h0     = (const float*)d_in[1];
  const float* emb    = (const float*)d_in[2];
  const float* conv_w = (const float*)d_in[3];
  const float* conv_b = (const float*)d_in[4];
  const float* w_ih   = (const float*)d_in[5];
  const float* w_hh   = (const float*)d_in[6];
  const float* b_ih   = (const float*)d_in[7];
  const float* b_hh   = (const float*)d_in[8];

  cudaFuncSetAttribute(lstm2_kernel,
                       cudaFuncAttributeMaxDynamicSharedMemorySize, RSMEM);

  // K1: conv GEMM with fused embedding gather
  sgemm_conv_kernel<<<dim3(NF_ / 128, M_ / 128), 128>>>(
      text, emb, conv_w, conv_b);

  // K2: x-gates GEMM (BN=256)
  sgemm_x_kernel<<<dim3(GATES / 256, M_ / 128), 256>>>(w_ih, b_ih, b_hh);

  // K3: whole recurrence in ONE persistent clustered launch (DSMEM exchange)
  lstm2_kernel<<<128, 128, RSMEM>>>(w_hh, h0, (float*)d_out);
}

// round 16
// speedup vs baseline: 1.0275x; 1.0275x over previous
#include <cuda_runtime.h>
#include <cstdint>
#include <cstddef>

// Problem constants
#define B_    256
#define S_    512
#define EMB_  256
#define KER_  5
#define NF_   256
#define HID_  128
#define T_    508            // S - KER + 1
#define M_    (T_ * B_)      // 130048 rows (r = t*B + b)
#define KCONV (KER_ * EMB_)  // 1280
#define GATES 512            // 4*HID

typedef unsigned long long u64;

// ---------------- f32x2 packed-FMA helpers (proven clean) ------------------
__device__ __forceinline__ void fma2(u64& d, u64 a, u64 b) {
  asm("fma.rn.f32x2 %0, %1, %2, %0;" : "+l"(d) : "l"(a), "l"(b));
}
__device__ __forceinline__ u64 pack2(float x, float y) {
  u64 r; asm("mov.b64 %0, {%1, %2};" : "=l"(r) : "f"(x), "f"(y)); return r;
}
__device__ __forceinline__ float2 unpack2(u64 p) {
  float2 f; asm("mov.b64 {%0, %1}, %2;" : "=f"(f.x), "=f"(f.y) : "l"(p));
  return f;
}
__device__ __forceinline__ uint32_t smem_addr_u32(const void* p) {
  uint32_t a;
  asm("{ .reg .u64 t; cvta.to.shared.u64 t, %1; cvt.u32.u64 %0, t; }"
      : "=r"(a) : "l"(p));
  return a;
}
__device__ __forceinline__ uint32_t cluster_rank() {
  uint32_t r; asm("mov.u32 %0, %%cluster_ctarank;" : "=r"(r)); return r;
}
__device__ __forceinline__ uint32_t mapa_u32(uint32_t la, uint32_t rank) {
  uint32_t r;
  asm("mapa.shared::cluster.u32 %0, %1, %2;" : "=r"(r) : "r"(la), "r"(rank));
  return r;
}
__device__ __forceinline__ void st_cluster_u64(uint32_t addr, u64 v) {
  asm volatile("st.shared::cluster.u64 [%0], %1;" :: "r"(addr), "l"(v)
               : "memory");
}

// Scratch (fp32 only)
__device__ float g_F [(size_t)M_ * NF_];         // conv+relu    [r][nf]
__device__ float g_Xg[(size_t)M_ * GATES];       // x-gates+bias [r][4H]

// ---------------------------------------------------------------------------
// K1: conv GEMM with FUSED embedding gather (kept from R15; measured fine).
// BM=BN=128, BK=16, 128 thr, 16x8/thread FFMA2, double-buffered, 2 CTAs/SM.
// ---------------------------------------------------------------------------
__global__ void __launch_bounds__(128, 2)
sgemm_conv_kernel(const int* __restrict__ text,
                  const float* __restrict__ emb,
                  const float* __restrict__ W,
                  const float* __restrict__ bias0) {
  __shared__ float As[2][16][128];
  __shared__ float Bs[2][16][128];

  const int tid  = threadIdx.x;
  const int row0 = blockIdx.y * 128;
  const int col0 = blockIdx.x * 128;
  const int tr   = (tid >> 4) << 4;
  const int tc   = (tid & 15) << 3;
  const int ms   = tid >> 2;
  const int kq   = (tid & 3) * 4;

  u64 acc2[8][8];
#pragma unroll
  for (int i = 0; i < 8; i++)
#pragma unroll
    for (int j = 0; j < 8; j++) acc2[i][j] = 0ull;

  const int tt = row0 >> 8;
  int bI[4];
#pragma unroll
  for (int i = 0; i < 4; i++) bI[i] = (row0 + ms + i * 32) & 255;

  size_t boff[4];
#pragma unroll
  for (int i = 0; i < 4; i++)
    boff[i] = (size_t)(col0 + ms + i * 32) * KCONV;

  const int KT = KCONV >> 4;   // 80

  {
    int s = tt, col = kq;
#pragma unroll
    for (int i = 0; i < 4; i++) {
      int m = ms + i * 32;
      int tok = text[bI[i] * S_ + s];
      float4 va = *(const float4*)(emb + (size_t)tok * EMB_ + col);
      float4 vb = *(const float4*)(W + boff[i] + kq);
      As[0][kq + 0][m] = va.x; As[0][kq + 1][m] = va.y;
      As[0][kq + 2][m] = va.z; As[0][kq + 3][m] = va.w;
      Bs[0][kq + 0][m] = vb.x; Bs[0][kq + 1][m] = vb.y;
      Bs[0][kq + 2][m] = vb.z; Bs[0][kq + 3][m] = vb.w;
    }
  }
  __syncthreads();

  for (int kt = 0; kt < KT; kt++) {
    const int cur = kt & 1;
    float4 pa[4], pb[4];
    const bool pf = (kt + 1 < KT);
    if (pf) {
      int c = ((kt + 1) << 4) + kq;
      int s = tt + (c >> 8), col = c & 255;
#pragma unroll
      for (int i = 0; i < 4; i++) {
        int tok = text[bI[i] * S_ + s];
        pa[i] = *(const float4*)(emb + (size_t)tok * EMB_ + col);
        pb[i] = *(const float4*)(W + boff[i] + c);
      }
    }
#pragma unroll
    for (int kk = 0; kk < 16; kk++) {
      ulonglong2 a01 = *(const ulonglong2*)&As[cur][kk][tr];
      ulonglong2 a23 = *(const ulonglong2*)&As[cur][kk][tr +  4];
      ulonglong2 a45 = *(const ulonglong2*)&As[cur][kk][tr +  8];
      ulonglong2 a67 = *(const ulonglong2*)&As[cur][kk][tr + 12];
      u64 av[8] = {a01.x, a01.y, a23.x, a23.y, a45.x, a45.y, a67.x, a67.y};
      float4 b03 = *(const float4*)&Bs[cur][kk][tc];
      float4 b47 = *(const float4*)&Bs[cur][kk][tc + 4];
      u64 bd[8];
      bd[0] = pack2(b03.x, b03.x); bd[1] = pack2(b03.y, b03.y);
      bd[2] = pack2(b03.z, b03.z); bd[3] = pack2(b03.w, b03.w);
      bd[4] = pack2(b47.x, b47.x); bd[5] = pack2(b47.y, b47.y);
      bd[6] = pack2(b47.z, b47.z); bd[7] = pack2(b47.w, b47.w);
#pragma unroll
      for (int i = 0; i < 8; i++)
#pragma unroll
        for (int j = 0; j < 8; j++) fma2(acc2[i][j], av[i], bd[j]);
    }
    if (pf) {
      const int nxt = cur ^ 1;
#pragma unroll
      for (int i = 0; i < 4; i++) {
        int m = ms + i * 32;
        As[nxt][kq + 0][m] = pa[i].x; As[nxt][kq + 1][m] = pa[i].y;
        As[nxt][kq + 2][m] = pa[i].z; As[nxt][kq + 3][m] = pa[i].w;
        Bs[nxt][kq + 0][m] = pb[i].x; Bs[nxt][kq + 1][m] = pb[i].y;
        Bs[nxt][kq + 2][m] = pb[i].z; Bs[nxt][kq + 3][m] = pb[i].w;
      }
    }
    __syncthreads();
  }

#pragma unroll
  for (int i = 0; i < 8; i++) {
    float vlo[8], vhi[8];
#pragma unroll
    for (int j = 0; j < 8; j++) {
      int n = col0 + tc + j;
      float2 p = unpack2(acc2[i][j]);
      vlo[j] = fmaxf(p.x + bias0[n], 0.f);
      vhi[j] = fmaxf(p.y + bias0[n], 0.f);
    }
    float* c0 = &g_F[(size_t)(row0 + tr + 2 * i)     * NF_ + col0 + tc];
    float* c1 = &g_F[(size_t)(row0 + tr + 2 * i + 1) * NF_ + col0 + tc];
    *(float4*)(c0)     = *(float4*)&vlo[0];
    *(float4*)(c0 + 4) = *(float4*)&vlo[4];
    *(float4*)(c1)     = *(float4*)&vhi[0];
    *(float4*)(c1 + 4) = *(float4*)&vhi[4];
  }
}

// ---------------------------------------------------------------------------
// K2: x-gates GEMM — REVERTED to R14's proven shape: BM=BN=128, BK=16,
// 128 thr, 16x8/thread, double-buffered, 2 CTAs/SM. (BN=256/1-CTA was the
// R15 regressor: xproj is compute-floor-bound; A traffic was never binding.)
// ---------------------------------------------------------------------------
__global__ void __launch_bounds__(128, 2)
sgemm_x_kernel(const float* __restrict__ W,
               const float* __restrict__ b_ih,
               const float* __restrict__ b_hh) {
  __shared__ float As[2][16][128];
  __shared__ float Bs[2][16][128];

  const int tid  = threadIdx.x;
  const int row0 = blockIdx.y * 128;
  const int col0 = blockIdx.x * 128;
  const int tr   = (tid >> 4) << 4;
  const int tc   = (tid & 15) << 3;
  const int ms   = tid >> 2;
  const int kq   = (tid & 3) * 4;

  u64 acc2[8][8];
#pragma unroll
  for (int i = 0; i < 8; i++)
#pragma unroll
    for (int j = 0; j < 8; j++) acc2[i][j] = 0ull;

  size_t aoff[4], boff[4];
#pragma unroll
  for (int i = 0; i < 4; i++) {
    int m = ms + i * 32;
    aoff[i] = (size_t)(row0 + m) * NF_;
    boff[i] = (size_t)(col0 + m) * NF_;
  }

  const int KT = NF_ >> 4;   // 16

#pragma unroll
  for (int i = 0; i < 4; i++) {
    int m = ms + i * 32;
    float4 va = *(const float4*)(g_F + aoff[i] + kq);
    float4 vb = *(const float4*)(W + boff[i] + kq);
    As[0][kq + 0][m] = va.x; As[0][kq + 1][m] = va.y;
    As[0][kq + 2][m] = va.z; As[0][kq + 3][m] = va.w;
    Bs[0][kq + 0][m] = vb.x; Bs[0][kq + 1][m] = vb.y;
    Bs[0][kq + 2][m] = vb.z; Bs[0][kq + 3][m] = vb.w;
  }
  __syncthreads();

  for (int kt = 0; kt < KT; kt++) {
    const int cur = kt & 1;
    float4 pa[4], pb[4];
    const bool pf = (kt + 1 < KT);
    if (pf) {
      int k0 = (kt + 1) << 4;
#pragma unroll
      for (int i = 0; i < 4; i++) {
        pa[i] = *(const float4*)(g_F + aoff[i] + k0 + kq);
        pb[i] = *(const float4*)(W + boff[i] + k0 + kq);
      }
    }
#pragma unroll
    for (int kk = 0; kk < 16; kk++) {
      ulonglong2 a01 = *(const ulonglong2*)&As[cur][kk][tr];
      ulonglong2 a23 = *(const ulonglong2*)&As[cur][kk][tr +  4];
      ulonglong2 a45 = *(const ulonglong2*)&As[cur][kk][tr +  8];
      ulonglong2 a67 = *(const ulonglong2*)&As[cur][kk][tr + 12];
      u64 av[8] = {a01.x, a01.y, a23.x, a23.y, a45.x, a45.y, a67.x, a67.y};
      float4 b03 = *(const float4*)&Bs[cur][kk][tc];
      float4 b47 = *(const float4*)&Bs[cur][kk][tc + 4];
      u64 bd[8];
      bd[0] = pack2(b03.x, b03.x); bd[1] = pack2(b03.y, b03.y);
      bd[2] = pack2(b03.z, b03.z); bd[3] = pack2(b03.w, b03.w);
      bd[4] = pack2(b47.x, b47.x); bd[5] = pack2(b47.y, b47.y);
      bd[6] = pack2(b47.z, b47.z); bd[7] = pack2(b47.w, b47.w);
#pragma unroll
      for (int i = 0; i < 8; i++)
#pragma unroll
        for (int j = 0; j < 8; j++) fma2(acc2[i][j], av[i], bd[j]);
    }
    if (pf) {
      const int nxt = cur ^ 1;
#pragma unroll
      for (int i = 0; i < 4; i++) {
        int m = ms + i * 32;
        As[nxt][kq + 0][m] = pa[i].x; As[nxt][kq + 1][m] = pa[i].y;
        As[nxt][kq + 2][m] = pa[i].z; As[nxt][kq + 3][m] = pa[i].w;
        Bs[nxt][kq + 0][m] = pb[i].x; Bs[nxt][kq + 1][m] = pb[i].y;
        Bs[nxt][kq + 2][m] = pb[i].z; Bs[nxt][kq + 3][m] = pb[i].w;
      }
    }
    __syncthreads();
  }

#pragma unroll
  for (int i = 0; i < 8; i++) {
    float vlo[8], vhi[8];
#pragma unroll
    for (int j = 0; j < 8; j++) {
      int n = col0 + tc + j;
      float2 p = unpack2(acc2[i][j]);
      float bb = b_ih[n] + b_hh[n];
      vlo[j] = p.x + bb;
      vhi[j] = p.y + bb;
    }
    float* c0 = &g_Xg[(size_t)(row0 + tr + 2 * i)     * GATES + col0 + tc];
    float* c1 = &g_Xg[(size_t)(row0 + tr + 2 * i + 1) * GATES + col0 + tc];
    *(float4*)(c0)     = *(float4*)&vlo[0];
    *(float4*)(c0 + 4) = *(float4*)&vlo[4];
    *(float4*)(c1)     = *(float4*)&vhi[0];
    *(float4*)(c1 + 4) = *(float4*)&vhi[4];
  }
}

// ---------------------------------------------------------------------------
// K3: persistent LSTM recurrence, cluster-of-2 DSMEM (R15 version kept:
// x-gate prefetch hidden under the cluster barrier, no redundant sync).
// ---------------------------------------------------------------------------
#define WP_FLOATS (128 * 64 * 4)             // 32768 floats = 128KB
#define HS_FLOATS (2 * 4 * 256)              // 2048 floats = 8KB
#define RSMEM     ((WP_FLOATS + HS_FLOATS) * 4)

__global__ void __launch_bounds__(128, 1) __cluster_dims__(2, 1, 1)
lstm2_kernel(const float* __restrict__ w_hh,
             const float* __restrict__ h0,
             float* __restrict__ out) {
  extern __shared__ float sm[];
  float* Wp = sm;                 // [k][jl][g], 64 jl of this half
  float* hs = sm + WP_FLOATS;     // [buf][b][2k..2k+1]

  const int tid = threadIdx.x;
  const int bid = blockIdx.x;
  const int jh  = bid & 1;
  const int bt  = bid >> 1;
  const uint32_t peer = cluster_rank() ^ 1u;

  for (int i = tid; i < WP_FLOATS; i += 128) {
    int k = i >> 8, rem = i & 255, jl = rem >> 2, g = rem & 3;
    Wp[i] = w_hh[(size_t)(g * 128 + jh * 64 + jl) * 128 + k];
  }
  {
    float4 v = ((const float4*)(h0 + bt * 4 * HID_))[tid];
    int b = tid >> 5, k4 = tid & 31;
    float* d = &hs[b * 256 + k4 * 8];
    *(float4*)(d)     = make_float4(v.x, v.x, v.y, v.y);
    *(float4*)(d + 4) = make_float4(v.z, v.z, v.w, v.w);
  }
  __syncthreads();

  const int jl = tid & 63;
  const int bp = tid >> 6;
  const int jg = jh * 64 + jl;
  const int b0 = bt * 4 + 2 * bp;
  const uint32_t hs_u32 = smem_addr_u32(hs);

  float c0 = 0.f, c1 = 0.f;

  float x0[4], x1[4];
  {
    const float* xg = g_Xg + (size_t)b0 * GATES;
#pragma unroll
    for (int g = 0; g < 4; g++) {
      x0[g] = xg[g * HID_ + jg];
      x1[g] = xg[GATES + g * HID_ + jg];
    }
  }

  for (int t = 0; t < T_; t++) {
    u64 aA0 = 0ull, aB0 = 0ull, aA1 = 0ull, aB1 = 0ull;
    const float* h0r = &hs[(t & 1) * 1024 + (2 * bp)     * 256];
    const float* h1r = &hs[(t & 1) * 1024 + (2 * bp + 1) * 256];
#pragma unroll 8
    for (int k = 0; k < HID_; k += 4) {
      ulonglong2 pa  = *(const ulonglong2*)(h0r + 2 * k);
      ulonglong2 pa2 = *(const ulonglong2*)(h0r + 2 * k + 4);
      ulonglong2 pb  = *(const ulonglong2*)(h1r + 2 * k);
      ulonglong2 pb2 = *(const ulonglong2*)(h1r + 2 * k + 4);
      u64 hd0[4] = {pa.x, pa.y, pa2.x, pa2.y};
      u64 hd1[4] = {pb.x, pb.y, pb2.x, pb2.y};
#pragma unroll
      for (int kk = 0; kk < 4; kk++) {
        ulonglong2 wv = *(const ulonglong2*)&Wp[((k + kk) * 64 + jl) * 4];
        fma2(aA0, hd0[kk], wv.x); fma2(aB0, hd0[kk], wv.y);
        fma2(aA1, hd1[kk], wv.x); fma2(aB1, hd1[kk], wv.y);
      }
    }

    float2 pA0 = unpack2(aA0), pB0 = unpack2(aB0);
    float2 pA1 = unpack2(aA1), pB1 = unpack2(aB1);

    float i0 = 1.f / (1.f + __expf(-(pA0.x + x0[0])));
    float f0 = 1.f / (1.f + __expf(-(pA0.y + x0[1])));
    float g0 = tanhf(pB0.x + x0[2]);
    float o0 = 1.f / (1.f + __expf(-(pB0.y + x0[3])));
    c0 = f0 * c0 + i0 * g0;
    float h0v = o0 * tanhf(c0);

    float i1 = 1.f / (1.f + __expf(-(pA1.x + x1[0])));
    float f1 = 1.f / (1.f + __expf(-(pA1.y + x1[1])));
    float g1 = tanhf(pB1.x + x1[2]);
    float o1 = 1.f / (1.f + __expf(-(pB1.y + x1[3])));
    c1 = f1 * c1 + i1 * g1;
    float h1v = o1 * tanhf(c1);

    if (t == T_ - 1) {
      out[b0 * HID_ + jg]        = h0v;
      out[(b0 + 1) * HID_ + jg]  = h1v;
    } else {
      const int fo0 = ((t + 1) & 1) * 1024 + (2 * bp) * 256 + 2 * jg;
      const int fo1 = fo0 + 256;
      u64 p0 = pack2(h0v, h0v);
      u64 p1 = pack2(h1v, h1v);
      *(u64*)&hs[fo0] = p0;
      *(u64*)&hs[fo1] = p1;
      st_cluster_u64(mapa_u32(hs_u32 + fo0 * 4, peer), p0);
      st_cluster_u64(mapa_u32(hs_u32 + fo1 * 4, peer), p1);

      const float* xg = g_Xg + ((size_t)(t + 1) * B_ + b0) * GATES;
#pragma unroll
      for (int g = 0; g < 4; g++) {
        x0[g] = xg[g * HID_ + jg];
        x1[g] = xg[GATES + g * HID_ + jg];
      }

      asm volatile("barrier.cluster.arrive.aligned;" ::: "memory");
      asm volatile("barrier.cluster.wait.aligned;"   ::: "memory");
    }
  }
}

// ---------------------------------------------------------------------------
extern "C" void kernel_launch(void* const* d_in, const int* in_sizes, int n_in,
                              void* d_out, int out_size) {
  const int*   text   = (const int*)  d_in[0];
  const float* h0     = (const float*)d_in[1];
  const float* emb    = (const float*)d_in[2];
  const float* conv_w = (const float*)d_in[3];
  const float* conv_b = (const float*)d_in[4];
  const float* w_ih   = (const float*)d_in[5];
  const float* w_hh   = (const float*)d_in[6];
  const float* b_ih   = (const float*)d_in[7];
  const float* b_hh   = (const float*)d_in[8];

  cudaFuncSetAttribute(lstm2_kernel,
                       cudaFuncAttributeMaxDynamicSharedMemorySize, RSMEM);

  // K1: conv GEMM with fused embedding gather
  sgemm_conv_kernel<<<dim3(NF_ / 128, M_ / 128), 128>>>(
      text, emb, conv_w, conv_b);

  // K2: x-gates GEMM (R14 proven shape)
  sgemm_x_kernel<<<dim3(GATES / 128, M_ / 128), 128>>>(w_ih, b_ih, b_hh);

  // K3: whole recurrence in ONE persistent clustered launch (DSMEM exchange)
  lstm2_kernel<<<128, 128, RSMEM>>>(w_hh, h0, (float*)d_out);
}